// round 4
// baseline (speedup 1.0000x reference)
#include <cuda_runtime.h>
#include <cuda_bf16.h>
#include <cstdint>

#define NN 50000
#define NE 640000
#define DD 128
#define NCLS 64

// ---------------- scratch (device globals; float4 => guaranteed 16B alignment) ----------------
__device__ float4 g_bufA[(size_t)NN * 32];   // 50000 x 128 floats
__device__ float4 g_bufB[(size_t)NN * 32];
__device__ int    g_cnt[NN];
__device__ int    g_off[NN + 1];
__device__ int    g_cur[NN];
__device__ float  g_dinv[NN];
__device__ int    g_col[NE];
__device__ int    g_src[NE];
__device__ int    g_dst[NE];
__device__ int    g_is64;

// ---------------- edge_index dtype detection + normalization ----------------
// If the buffer holds int64 little-endian values < 2^31, every odd 32-bit word
// (hi word) is 0. Sample 2048 odd words inside the first 2*NE words (safe to
// read under BOTH interpretations). Any nonzero => int32 layout.
__global__ void detect_kernel(const unsigned int* __restrict__ raw) {
    __shared__ int s_any;
    if (threadIdx.x == 0) s_any = 0;
    __syncthreads();
    int any = 0;
    for (int i = threadIdx.x; i < 2048; i += blockDim.x) {
        size_t k = (size_t)i * (NE / 2048);          // 0 .. NE-1 spread
        if (raw[2 * k + 1] != 0u) any = 1;
    }
    if (any) atomicOr(&s_any, 1);
    __syncthreads();
    if (threadIdx.x == 0) g_is64 = s_any ? 0 : 1;
}

__global__ void normalize_kernel(const int* __restrict__ raw) {
    int e = blockIdx.x * blockDim.x + threadIdx.x;
    if (e >= NE) return;
    int is64 = g_is64;
    int s, d;
    if (is64) {
        s = raw[2 * (size_t)e];            // lo word of src int64
        d = raw[2 * ((size_t)NE + e)];     // lo word of dst int64
    } else {
        s = raw[e];
        d = raw[NE + e];
    }
    // defensive clamp: never trap on surprises
    s = min(max(s, 0), NN - 1);
    d = min(max(d, 0), NN - 1);
    g_src[e] = s;
    g_dst[e] = d;
}

// ---------------- CSR build ----------------
__global__ void zero_cnt_kernel() {
    int i = blockIdx.x * blockDim.x + threadIdx.x;
    if (i < NN) g_cnt[i] = 0;
}

__global__ void hist_kernel() {
    int e = blockIdx.x * blockDim.x + threadIdx.x;
    if (e < NE) atomicAdd(&g_cnt[g_dst[e]], 1);
}

// single-block exclusive scan over 50000 counters; also emits dinv and cursor copy
__global__ void scan_kernel() {
    __shared__ int wsum[32];
    int lane = threadIdx.x & 31;
    int wid  = threadIdx.x >> 5;
    int carry = 0;
    for (int base = 0; base < NN; base += 1024) {
        int i = base + threadIdx.x;
        int v = (i < NN) ? g_cnt[i] : 0;
        int inc = v;
        #pragma unroll
        for (int d = 1; d < 32; d <<= 1) {
            int t = __shfl_up_sync(0xffffffffu, inc, d);
            if (lane >= d) inc += t;
        }
        if (lane == 31) wsum[wid] = inc;
        __syncthreads();
        if (wid == 0) {
            int s = wsum[lane];
            #pragma unroll
            for (int d = 1; d < 32; d <<= 1) {
                int t = __shfl_up_sync(0xffffffffu, s, d);
                if (lane >= d) s += t;
            }
            wsum[lane] = s;
        }
        __syncthreads();
        int add  = carry + (wid > 0 ? wsum[wid - 1] : 0);
        int excl = add + inc - v;
        if (i < NN) {
            g_off[i]  = excl;
            g_cur[i]  = excl;
            g_dinv[i] = rsqrtf((float)(v + 1));  // +1 self-loop
        }
        carry += wsum[31];
        __syncthreads();
    }
    if (threadIdx.x == 0) g_off[NN] = carry;
}

__global__ void fill_kernel() {
    int e = blockIdx.x * blockDim.x + threadIdx.x;
    if (e < NE) {
        int p = atomicAdd(&g_cur[g_dst[e]], 1);
        g_col[p] = g_src[e];
    }
}

// ---------------- sparse propagate: out[i] = dinv[i]*( sum_e dinv[src]*X[src] + dinv[i]*X[i] )
// one warp per node; lane l owns dims [4l, 4l+4). FROM_X: read external x (16B-aligned
// harness buffer), else read g_bufB. Always writes g_bufA.
template<bool FROM_X>
__global__ void prop_kernel(const float* __restrict__ xin) {
    int warp = (blockIdx.x * blockDim.x + threadIdx.x) >> 5;
    int lane = threadIdx.x & 31;
    if (warp >= NN) return;
    const float4* X4 = FROM_X ? (const float4*)xin : (const float4*)g_bufB;
    int i = warp;
    float di = g_dinv[i];
    float4 v = X4[(size_t)i * 32 + lane];
    float ax = di * v.x, ay = di * v.y, az = di * v.z, aw = di * v.w;
    int e  = g_off[i];
    int e1 = g_off[i + 1];
    for (; e + 4 <= e1; e += 4) {
        int s0 = g_col[e + 0], s1 = g_col[e + 1], s2 = g_col[e + 2], s3 = g_col[e + 3];
        float w0 = g_dinv[s0], w1 = g_dinv[s1], w2 = g_dinv[s2], w3 = g_dinv[s3];
        float4 v0 = X4[(size_t)s0 * 32 + lane];
        float4 v1 = X4[(size_t)s1 * 32 + lane];
        float4 v2 = X4[(size_t)s2 * 32 + lane];
        float4 v3 = X4[(size_t)s3 * 32 + lane];
        ax += w0 * v0.x + w1 * v1.x + w2 * v2.x + w3 * v3.x;
        ay += w0 * v0.y + w1 * v1.y + w2 * v2.y + w3 * v3.y;
        az += w0 * v0.z + w1 * v1.z + w2 * v2.z + w3 * v3.z;
        aw += w0 * v0.w + w1 * v1.w + w2 * v2.w + w3 * v3.w;
    }
    for (; e < e1; ++e) {
        int s = g_col[e];
        float w = g_dinv[s];
        float4 vv = X4[(size_t)s * 32 + lane];
        ax += w * vv.x; ay += w * vv.y; az += w * vv.z; aw += w * vv.w;
    }
    float4 o;
    o.x = ax * di; o.y = ay * di; o.z = az * di; o.w = aw * di;
    g_bufA[(size_t)i * 32 + lane] = o;
}

// ---------------- dense fp32 GEMM: C[M,N] = A[M,128] @ W[128,N] + bias (opt relu)
// Static smem only (<48KB): BK=32 chunks. 256 threads = 16x16, microtile 8 x (N/16).
// SRC_B: A = g_bufB else g_bufA.  TO_OUT: C = outp else g_bufB.
template<int N, bool RELU, bool SRC_B, bool TO_OUT>
__global__ void gemm_kernel(const float* __restrict__ W, const float* __restrict__ bias,
                            float* __restrict__ outp) {
    const float4* A4 = SRC_B ? (const float4*)g_bufB : (const float4*)g_bufA;
    float* C = TO_OUT ? outp : (float*)g_bufB;

    __shared__ alignas(16) float As[128 * 33];   // 16.9 KB, pad 33 breaks bank conflicts
    __shared__ alignas(16) float Ws[32 * N];     // 16 KB (N=128) / 8 KB (N=64)

    int m0 = blockIdx.x * 128;
    int tx = threadIdx.x & 15;
    int ty = threadIdx.x >> 4;
    constexpr int TNc = N / 16;

    float acc[8][TNc];
    #pragma unroll
    for (int r = 0; r < 8; ++r)
        #pragma unroll
        for (int c = 0; c < TNc; ++c) acc[r][c] = 0.f;

    for (int kb = 0; kb < 128; kb += 32) {
        // load A tile: 128 rows x 32 cols (kb..kb+31), float4 global, scalar smem store
        for (int f = threadIdx.x; f < 128 * 8; f += 256) {
            int row = f >> 3, j = f & 7;
            float4 v = make_float4(0.f, 0.f, 0.f, 0.f);
            int gr = m0 + row;
            if (gr < NN) v = A4[(size_t)gr * 32 + (kb >> 2) + j];
            float* p = As + row * 33 + j * 4;
            p[0] = v.x; p[1] = v.y; p[2] = v.z; p[3] = v.w;
        }
        // load W rows kb..kb+31 (contiguous, harness pointer => 16B aligned)
        for (int f = threadIdx.x; f < 32 * N / 4; f += 256)
            ((float4*)Ws)[f] = ((const float4*)W)[kb * (N / 4) + f];
        __syncthreads();

        #pragma unroll
        for (int k = 0; k < 32; ++k) {
            float a[8];
            #pragma unroll
            for (int r = 0; r < 8; ++r) a[r] = As[(ty * 8 + r) * 33 + k];
            float b[TNc];
            #pragma unroll
            for (int c = 0; c < TNc; ++c) b[c] = Ws[k * N + tx + 16 * c];
            #pragma unroll
            for (int r = 0; r < 8; ++r)
                #pragma unroll
                for (int c = 0; c < TNc; ++c)
                    acc[r][c] += a[r] * b[c];
        }
        __syncthreads();
    }

    #pragma unroll
    for (int r = 0; r < 8; ++r) {
        int gr = m0 + ty * 8 + r;
        if (gr < NN) {
            #pragma unroll
            for (int c = 0; c < TNc; ++c) {
                int col = tx + 16 * c;
                float v = acc[r][c] + bias[col];
                if (RELU) v = fmaxf(v, 0.f);
                C[(size_t)gr * N + col] = v;
            }
        }
    }
}

// ---------------- launch ----------------
extern "C" void kernel_launch(void* const* d_in, const int* in_sizes, int n_in,
                              void* d_out, int out_size) {
    const float* x  = (const float*)d_in[0];
    const float* W1 = (const float*)d_in[2];
    const float* b1 = (const float*)d_in[3];
    const float* W2 = (const float*)d_in[4];
    const float* b2 = (const float*)d_in[5];
    const float* Wl = (const float*)d_in[6];
    const float* bl = (const float*)d_in[7];
    float*       out = (float*)d_out;

    // edge_index: dtype-agnostic normalization (int32 vs int64 detected on device)
    detect_kernel<<<1, 256>>>((const unsigned int*)d_in[1]);
    normalize_kernel<<<(NE + 255) / 256, 256>>>((const int*)d_in[1]);

    // CSR build (re-done every call; deterministic work, order-only atomics)
    zero_cnt_kernel<<<(NN + 255) / 256, 256>>>();
    hist_kernel<<<(NE + 255) / 256, 256>>>();
    scan_kernel<<<1, 1024>>>();
    fill_kernel<<<(NE + 255) / 256, 256>>>();

    dim3 pgrid((NN + 7) / 8);
    dim3 ggrid((NN + 127) / 128);

    // layer 1: propagate(x) -> bufA ; bufA @ W1 + b1, relu -> bufB
    prop_kernel<true><<<pgrid, 256>>>(x);
    gemm_kernel<128, true, false, false><<<ggrid, 256>>>(W1, b1, nullptr);
    // layer 2: propagate(bufB) -> bufA ; bufA @ W2 + b2, relu -> bufB
    prop_kernel<false><<<pgrid, 256>>>(nullptr);
    gemm_kernel<128, true, false, false><<<ggrid, 256>>>(W2, b2, nullptr);
    // head: bufB @ Wl + bl -> out
    gemm_kernel<64, false, true, true><<<ggrid, 256>>>(Wl, bl, out);
}